// round 7
// baseline (speedup 1.0000x reference)
#include <cuda_runtime.h>
#include <cstdint>

#define B_  8
#define C_  64
#define H_  64
#define W_  64
#define NN  9
#define M_  18
#define HP  66
#define KTOT 576

typedef unsigned long long ull;

__device__ float  g_offset[B_ * M_ * H_ * W_];
__device__ float  g_Wp[KTOT * C_];       // permuted: [(n*64+ci)*64 + co]
__device__ float2 g_Wo2[64 * 9 * 10];    // paired offset-conv weights [ci*9+j][10]

// ---------------- helpers ----------------
__device__ __forceinline__ void ffma2(ull& d, ull a, ull b) {
    asm("fma.rn.f32x2 %0, %1, %2, %0;" : "+l"(d) : "l"(a), "l"(b));
}
__device__ __forceinline__ float2 unpack2(ull v) {
    float2 r; asm("mov.b64 {%0, %1}, %2;" : "=f"(r.x), "=f"(r.y) : "l"(v)); return r;
}
__device__ __forceinline__ ull dup2(float v) {
    ull r; asm("mov.b64 %0, {%1, %1};" : "=l"(r) : "f"(v)); return r;
}
__device__ __forceinline__ ull pack2(float lo, float hi) {
    ull r; asm("mov.b64 %0, {%1, %2};" : "=l"(r) : "f"(lo), "f"(hi)); return r;
}

// ---------------------------------------------------------------------------
// K1: offset conv (FFMA2 over m-pairs), weights read via __ldg (L1-cached).
// z==8 slice: prep g_Wp (permute) + g_Wo2 (pairing).
// ---------------------------------------------------------------------------
#define K1_SMEM (64 * 324 * 4)   // 82944 B (x tile only)

__global__ __launch_bounds__(256, 2)
void k1_offset_conv(const float* __restrict__ x,
                    const float* __restrict__ Woff,
                    const float* __restrict__ boff,
                    const float* __restrict__ Wc) {
    if (blockIdx.z == 8) {
        int base = (blockIdx.y * 4 + blockIdx.x) * 256 + threadIdx.x;
        for (int i = base; i < KTOT * C_; i += 16 * 256) {
            int kp = i >> 6;
            int co = i & 63;
            int n  = kp >> 6;
            int ci = kp & 63;
            g_Wp[i] = Wc[co * KTOT + ci * 9 + n];
        }
        for (int i = base; i < 64 * 81; i += 16 * 256) {
            int ci = i / 81;
            int rem = i % 81;
            int j = rem / 9, t = rem % 9;
            g_Wo2[(ci * 9 + j) * 10 + t] =
                make_float2(Woff[(2 * j)     * 576 + ci * 9 + t],
                            Woff[(2 * j + 1) * 576 + ci * 9 + t]);
        }
        return;
    }

    extern __shared__ float smem[];
    float* xs = smem;                 // [ci][18][18]

    const int tid = threadIdx.x;
    const int b   = blockIdx.z;
    const int th0 = blockIdx.y * 16;
    const int tw0 = blockIdx.x * 16;

    const float* xb = x + (size_t)b * C_ * H_ * W_;
    for (int idx = tid; idx < 64 * 324; idx += 256) {
        int ci = idx / 324;
        int rem = idx % 324;
        int r = rem / 18, c = rem % 18;
        int gh = th0 + r - 1, gw = tw0 + c - 1;
        float v = 0.f;
        if ((unsigned)gh < H_ && (unsigned)gw < W_)
            v = xb[(ci * H_ + gh) * W_ + gw];
        xs[idx] = v;
    }
    __syncthreads();

    const int lh = tid >> 4, lw = tid & 15;
    ull acc[9];
#pragma unroll
    for (int j = 0; j < 9; j++) acc[j] = pack2(boff[2 * j], boff[2 * j + 1]);

    for (int ci = 0; ci < 64; ci++) {
        ull xd[9];
        const float* xc = xs + ci * 324 + lh * 18 + lw;
#pragma unroll
        for (int u = 0; u < 3; u++)
#pragma unroll
            for (int v = 0; v < 3; v++)
                xd[u * 3 + v] = dup2(xc[u * 18 + v]);
#pragma unroll
        for (int j = 0; j < 9; j++) {
            const float2* wp = g_Wo2 + (ci * 9 + j) * 10;
            longlong2 wA = __ldg((const longlong2*)wp);
            longlong2 wB = __ldg((const longlong2*)(wp + 2));
            longlong2 wC = __ldg((const longlong2*)(wp + 4));
            longlong2 wD = __ldg((const longlong2*)(wp + 6));
            ull       wE = __ldg((const unsigned long long*)(wp + 8));
            ffma2(acc[j], (ull)wA.x, xd[0]); ffma2(acc[j], (ull)wA.y, xd[1]);
            ffma2(acc[j], (ull)wB.x, xd[2]); ffma2(acc[j], (ull)wB.y, xd[3]);
            ffma2(acc[j], (ull)wC.x, xd[4]); ffma2(acc[j], (ull)wC.y, xd[5]);
            ffma2(acc[j], (ull)wD.x, xd[6]); ffma2(acc[j], (ull)wD.y, xd[7]);
            ffma2(acc[j], wE,        xd[8]);
        }
    }

    const int h = th0 + lh, w = tw0 + lw;
#pragma unroll
    for (int j = 0; j < 9; j++) {
        float2 v = unpack2(acc[j]);
        g_offset[((b * M_ + 2 * j)     * H_ + h) * W_ + w] = v.x;
        g_offset[((b * M_ + 2 * j + 1) * H_ + h) * W_ + w] = v.y;
    }
}

// ---------------------------------------------------------------------------
// K2: fused bilinear sampling + GEMM.  Block = (b, 1 row) = 64 px, 128 thr.
// Thread tile 8px x 4co. Warp = 2pg x 16cg -> A dedup'd (1 wf per LDS.128).
// K permuted (k' = n*64+ci): meta loaded once per chunk per px.
// ---------------------------------------------------------------------------
#define NSAMP 576
#define SM_Q  0                                  // ushort4[576] = 4608
#define SM_G  (SM_Q + NSAMP * 8)                 // float4[576]  = 9216
#define SM_XO (SM_G + NSAMP * 16)                // [64 ci][64 px] = 16384
#define SM_W  (SM_XO + 64 * 64 * 4)              // [64 k][64 co]  = 16384
#define K2_SMEM (SM_W + 64 * 64 * 4)             // 46592

__global__ __launch_bounds__(128, 4)
void k2_sample_gemm(const float* __restrict__ x, float* __restrict__ out) {
    extern __shared__ char smc[];
    ushort4* s_q  = (ushort4*)(smc + SM_Q);
    float4*  s_g  = (float4*)(smc + SM_G);
    float*   xo_s = (float*)(smc + SM_XO);
    float*   w_s  = (float*)(smc + SM_W);

    const int tid = threadIdx.x;
    const int h   = blockIdx.x;
    const int b   = blockIdx.y;

    // ---- Phase A: 4 clamped element-offsets + pre-zeroed weights -----------
    for (int t = tid; t < NSAMP; t += 128) {
        int n  = t >> 6;
        int px = t & 63;
        float offx = g_offset[((b * M_ + n)     * H_ + h) * W_ + px];
        float offy = g_offset[((b * M_ + 9 + n) * H_ + h) * W_ + px];
        float pX = (float)(h + 1)  + (float)(n / 3 - 1) + offx;
        float pY = (float)(px + 1) + (float)(n % 3 - 1) + offy;
        float fx = floorf(pX), fy = floorf(pY);
        int x0 = min(max((int)fx,     0), HP - 1);
        int x1 = min(max((int)fx + 1, 0), HP - 1);
        int y0 = min(max((int)fy,     0), HP - 1);
        int y1 = min(max((int)fy + 1, 0), HP - 1);
        float pxc = fminf(fmaxf(pX, 0.f), (float)(HP - 1));
        float pyc = fminf(fmaxf(pY, 0.f), (float)(HP - 1));
        float gx0 = 1.f + ((float)x0 - pxc);
        float gx1 = 1.f - ((float)x1 - pxc);
        float gy0 = 1.f + ((float)y0 - pyc);
        float gy1 = 1.f - ((float)y1 - pyc);
        int ix0 = x0 - 1, iy0 = y0 - 1, ix1 = x1 - 1, iy1 = y1 - 1;
        bool vx0 = (unsigned)ix0 < H_, vy0 = (unsigned)iy0 < W_;
        bool vx1 = (unsigned)ix1 < H_, vy1 = (unsigned)iy1 < W_;
        int cx0 = min(max(ix0, 0), H_ - 1);
        int cx1 = min(max(ix1, 0), H_ - 1);
        int cy0 = min(max(iy0, 0), W_ - 1);
        int cy1 = min(max(iy1, 0), W_ - 1);
        s_q[t] = make_ushort4((unsigned short)((cx0 << 6) + cy0),
                              (unsigned short)((cx1 << 6) + cy1),
                              (unsigned short)((cx0 << 6) + cy1),
                              (unsigned short)((cx1 << 6) + cy0));
        s_g[t] = make_float4(vx0 && vy0 ? gx0 * gy0 : 0.f,
                             vx1 && vy1 ? gx1 * gy1 : 0.f,
                             vx0 && vy1 ? gx0 * gy1 : 0.f,
                             vx1 && vy0 ? gx1 * gy0 : 0.f);
    }

    const int px   = tid & 63;        // gather: fixed pixel
    const int half = tid >> 6;        // gather: ci half (0/1)
    const int pg   = tid >> 4;        // GEMM: 8 groups x 8 px
    const int cg   = tid & 15;        // GEMM: 16 groups x 4 co
    const float* xbase = x + (size_t)b * C_ * H_ * W_;

    ull acc[4][4];                    // [co][px pair]
#pragma unroll
    for (int i = 0; i < 4; i++)
#pragma unroll
        for (int j = 0; j < 4; j++) acc[i][j] = 0ull;

    for (int n = 0; n < NN; n++) {
        __syncthreads();   // prev GEMM done reading xo_s/w_s (covers Phase A at n=0)

        // B chunk: w_s[k][co], k = ci within chunk n
        {
            const float4* src = (const float4*)(g_Wp + n * 4096);
            float4* dst = (float4*)w_s;
#pragma unroll
            for (int j = 0; j < 8; j++)
                dst[j * 128 + tid] = src[j * 128 + tid];
        }

        // gather: meta once, 32 ci per thread
        {
            ushort4 q = s_q[n * 64 + px];
            float4  g = s_g[n * 64 + px];
#pragma unroll 4
            for (int i = 0; i < 32; i++) {
                int ci = half * 32 + i;
                const float* xc = xbase + (ci << 12);
                float v = g.x * __ldg(xc + q.x) + g.y * __ldg(xc + q.y)
                        + g.z * __ldg(xc + q.z) + g.w * __ldg(xc + q.w);
                xo_s[ci * 64 + px] = v;
            }
        }
        __syncthreads();

        // GEMM chunk: 64 kk, 16 FFMA2/kk
#pragma unroll 4
        for (int kk = 0; kk < 64; kk++) {
            float4 a0 = *(const float4*)&xo_s[kk * 64 + pg * 8];
            float4 a1 = *(const float4*)&xo_s[kk * 64 + pg * 8 + 4];
            float4 w  = *(const float4*)&w_s[kk * 64 + cg * 4];
            ull a01 = ((const ull*)&a0)[0];
            ull a23 = ((const ull*)&a0)[1];
            ull a45 = ((const ull*)&a1)[0];
            ull a67 = ((const ull*)&a1)[1];
            ull w0 = dup2(w.x), w1 = dup2(w.y), w2 = dup2(w.z), w3 = dup2(w.w);
            ffma2(acc[0][0], w0, a01); ffma2(acc[0][1], w0, a23);
            ffma2(acc[0][2], w0, a45); ffma2(acc[0][3], w0, a67);
            ffma2(acc[1][0], w1, a01); ffma2(acc[1][1], w1, a23);
            ffma2(acc[1][2], w1, a45); ffma2(acc[1][3], w1, a67);
            ffma2(acc[2][0], w2, a01); ffma2(acc[2][1], w2, a23);
            ffma2(acc[2][2], w2, a45); ffma2(acc[2][3], w2, a67);
            ffma2(acc[3][0], w3, a01); ffma2(acc[3][1], w3, a23);
            ffma2(acc[3][2], w3, a45); ffma2(acc[3][3], w3, a67);
        }
    }

    // ---- Epilogue ----------------------------------------------------------
#pragma unroll
    for (int c = 0; c < 4; c++) {
        int co = cg * 4 + c;
        float* ob = &out[(((size_t)b * C_ + co) * H_ + h) * W_ + pg * 8];
        float2 p0 = unpack2(acc[c][0]);
        float2 p1 = unpack2(acc[c][1]);
        float2 p2 = unpack2(acc[c][2]);
        float2 p3 = unpack2(acc[c][3]);
        *(float4*)ob       = make_float4(p0.x, p0.y, p1.x, p1.y);
        *(float4*)(ob + 4) = make_float4(p2.x, p2.y, p3.x, p3.y);
    }
}

// ---------------------------------------------------------------------------
extern "C" void kernel_launch(void* const* d_in, const int* in_sizes, int n_in,
                              void* d_out, int out_size) {
    const float* x     = (const float*)d_in[0];
    const float* Woff  = (const float*)d_in[1];
    const float* boff  = (const float*)d_in[2];
    const float* Wconv = (const float*)d_in[3];
    float* out = (float*)d_out;

    cudaFuncSetAttribute(k1_offset_conv,
                         cudaFuncAttributeMaxDynamicSharedMemorySize, K1_SMEM);
    cudaFuncSetAttribute(k2_sample_gemm,
                         cudaFuncAttributeMaxDynamicSharedMemorySize, K2_SMEM);

    k1_offset_conv<<<dim3(4, 4, 9), 256, K1_SMEM>>>(x, Woff, boff, Wconv);
    k2_sample_gemm<<<dim3(H_, B_), 128, K2_SMEM>>>(x, out);
}

// round 8
// speedup vs baseline: 1.1983x; 1.1983x over previous
#include <cuda_runtime.h>
#include <cstdint>

#define B_  8
#define C_  64
#define H_  64
#define W_  64
#define NN  9
#define M_  18
#define HP  66
#define KTOT 576

typedef unsigned long long ull;

__device__ float g_offset[B_ * M_ * H_ * W_];
__device__ float g_Wp[KTOT * C_];   // permuted: [(n*64+ci)*64 + co]

// ---------------- helpers ----------------
__device__ __forceinline__ void ffma2(ull& d, ull a, ull b) {
    asm("fma.rn.f32x2 %0, %1, %2, %0;" : "+l"(d) : "l"(a), "l"(b));
}
__device__ __forceinline__ float2 unpack2(ull v) {
    float2 r; asm("mov.b64 {%0, %1}, %2;" : "=f"(r.x), "=f"(r.y) : "l"(v)); return r;
}
__device__ __forceinline__ ull dup2(float v) {
    ull r; asm("mov.b64 %0, {%1, %1};" : "=l"(r) : "f"(v)); return r;
}
__device__ __forceinline__ ull pack2(float lo, float hi) {
    ull r; asm("mov.b64 %0, {%1, %2};" : "=l"(r) : "f"(lo), "f"(hi)); return r;
}

// ---------------------------------------------------------------------------
// K1: offset conv (FFMA2 over m-pairs), weights staged in smem (R6 form).
// z==8 slice preps permuted g_Wp.
// ---------------------------------------------------------------------------
#define K1_SMEM ((64*324 + 64*9*10*2) * 4)   // 129024 B

__global__ __launch_bounds__(256, 1)
void k1_offset_conv(const float* __restrict__ x,
                    const float* __restrict__ Woff,
                    const float* __restrict__ boff,
                    const float* __restrict__ Wc) {
    if (blockIdx.z == 8) {
        int base = (blockIdx.y * 4 + blockIdx.x) * 256 + threadIdx.x;
        for (int i = base; i < KTOT * C_; i += 16 * 256) {
            int kp = i >> 6;
            int co = i & 63;
            int n  = kp >> 6;
            int ci = kp & 63;
            g_Wp[i] = Wc[co * KTOT + ci * 9 + n];
        }
        return;
    }

    extern __shared__ float smem[];
    float*  xs  = smem;                        // [ci][18][18]
    float2* ws2 = (float2*)(smem + 64 * 324);  // [ci][9][10]

    const int tid = threadIdx.x;
    const int b   = blockIdx.z;
    const int th0 = blockIdx.y * 16;
    const int tw0 = blockIdx.x * 16;

    const float* xb = x + (size_t)b * C_ * H_ * W_;
    for (int idx = tid; idx < 64 * 324; idx += 256) {
        int ci = idx / 324;
        int rem = idx % 324;
        int r = rem / 18, c = rem % 18;
        int gh = th0 + r - 1, gw = tw0 + c - 1;
        float v = 0.f;
        if ((unsigned)gh < H_ && (unsigned)gw < W_)
            v = xb[(ci * H_ + gh) * W_ + gw];
        xs[idx] = v;
    }
    for (int idx = tid; idx < 64 * 81; idx += 256) {
        int ci = idx / 81;
        int rem = idx % 81;
        int j = rem / 9, t = rem % 9;
        ws2[(ci * 9 + j) * 10 + t] =
            make_float2(Woff[(2 * j)     * 576 + ci * 9 + t],
                        Woff[(2 * j + 1) * 576 + ci * 9 + t]);
    }
    __syncthreads();

    const int lh = tid >> 4, lw = tid & 15;
    ull acc[9];
#pragma unroll
    for (int j = 0; j < 9; j++) acc[j] = pack2(boff[2 * j], boff[2 * j + 1]);

    for (int ci = 0; ci < 64; ci++) {
        ull xd[9];
        const float* xc = xs + ci * 324 + lh * 18 + lw;
#pragma unroll
        for (int u = 0; u < 3; u++)
#pragma unroll
            for (int v = 0; v < 3; v++)
                xd[u * 3 + v] = dup2(xc[u * 18 + v]);
#pragma unroll
        for (int j = 0; j < 9; j++) {
            const ulonglong2* wp = (const ulonglong2*)(ws2 + (ci * 9 + j) * 10);
            ulonglong2 wA = wp[0];
            ulonglong2 wB = wp[1];
            ulonglong2 wC = wp[2];
            ulonglong2 wD = wp[3];
            ull        wE = *(const ull*)(ws2 + (ci * 9 + j) * 10 + 8);
            ffma2(acc[j], wA.x, xd[0]); ffma2(acc[j], wA.y, xd[1]);
            ffma2(acc[j], wB.x, xd[2]); ffma2(acc[j], wB.y, xd[3]);
            ffma2(acc[j], wC.x, xd[4]); ffma2(acc[j], wC.y, xd[5]);
            ffma2(acc[j], wD.x, xd[6]); ffma2(acc[j], wD.y, xd[7]);
            ffma2(acc[j], wE,   xd[8]);
        }
    }

    const int h = th0 + lh, w = tw0 + lw;
#pragma unroll
    for (int j = 0; j < 9; j++) {
        float2 v = unpack2(acc[j]);
        g_offset[((b * M_ + 2 * j)     * H_ + h) * W_ + w] = v.x;
        g_offset[((b * M_ + 2 * j + 1) * H_ + h) * W_ + w] = v.y;
    }
}

// ---------------------------------------------------------------------------
// K2: fused bilinear sampling + GEMM.  Block = (b, 1 row) = 64 px, 128 thr.
// Thread tile 8px x 4co; warp = 2pg x 16cg (A dedup'd to 1 wf per LDS.128).
// 18 chunks of 32 k-rows -> smem 29.5KB -> 5 blocks/SM.
// ---------------------------------------------------------------------------
#define NSAMP 576
#define CK    32                                 // k rows per chunk
#define SM_Q  0                                  // ushort4[576] = 4608
#define SM_G  (SM_Q + NSAMP * 8)                 // float4[576]  = 9216
#define SM_XO (SM_G + NSAMP * 16)                // [32][64] = 8192
#define SM_W  (SM_XO + CK * 64 * 4)              // [32][64] = 8192
#define K2_SMEM (SM_W + CK * 64 * 4)             // 30208

__global__ __launch_bounds__(128, 5)
void k2_sample_gemm(const float* __restrict__ x, float* __restrict__ out) {
    extern __shared__ char smc[];
    ushort4* s_q  = (ushort4*)(smc + SM_Q);
    float4*  s_g  = (float4*)(smc + SM_G);
    float*   xo_s = (float*)(smc + SM_XO);
    float*   w_s  = (float*)(smc + SM_W);

    const int tid = threadIdx.x;
    const int h   = blockIdx.x;
    const int b   = blockIdx.y;

    // ---- Phase A: 4 clamped element-offsets + pre-zeroed weights -----------
    for (int t = tid; t < NSAMP; t += 128) {
        int n  = t >> 6;
        int px = t & 63;
        float offx = g_offset[((b * M_ + n)     * H_ + h) * W_ + px];
        float offy = g_offset[((b * M_ + 9 + n) * H_ + h) * W_ + px];
        float pX = (float)(h + 1)  + (float)(n / 3 - 1) + offx;
        float pY = (float)(px + 1) + (float)(n % 3 - 1) + offy;
        float fx = floorf(pX), fy = floorf(pY);
        int x0 = min(max((int)fx,     0), HP - 1);
        int x1 = min(max((int)fx + 1, 0), HP - 1);
        int y0 = min(max((int)fy,     0), HP - 1);
        int y1 = min(max((int)fy + 1, 0), HP - 1);
        float pxc = fminf(fmaxf(pX, 0.f), (float)(HP - 1));
        float pyc = fminf(fmaxf(pY, 0.f), (float)(HP - 1));
        float gx0 = 1.f + ((float)x0 - pxc);
        float gx1 = 1.f - ((float)x1 - pxc);
        float gy0 = 1.f + ((float)y0 - pyc);
        float gy1 = 1.f - ((float)y1 - pyc);
        int ix0 = x0 - 1, iy0 = y0 - 1, ix1 = x1 - 1, iy1 = y1 - 1;
        bool vx0 = (unsigned)ix0 < H_, vy0 = (unsigned)iy0 < W_;
        bool vx1 = (unsigned)ix1 < H_, vy1 = (unsigned)iy1 < W_;
        int cx0 = min(max(ix0, 0), H_ - 1);
        int cx1 = min(max(ix1, 0), H_ - 1);
        int cy0 = min(max(iy0, 0), W_ - 1);
        int cy1 = min(max(iy1, 0), W_ - 1);
        s_q[t] = make_ushort4((unsigned short)((cx0 << 6) + cy0),
                              (unsigned short)((cx1 << 6) + cy1),
                              (unsigned short)((cx0 << 6) + cy1),
                              (unsigned short)((cx1 << 6) + cy0));
        s_g[t] = make_float4(vx0 && vy0 ? gx0 * gy0 : 0.f,
                             vx1 && vy1 ? gx1 * gy1 : 0.f,
                             vx0 && vy1 ? gx0 * gy1 : 0.f,
                             vx1 && vy0 ? gx1 * gy0 : 0.f);
    }

    const int px   = tid & 63;        // gather: fixed pixel
    const int half = tid >> 6;        // gather: 16-ci half of chunk
    const int pg   = tid >> 4;        // GEMM: 8 groups x 8 px
    const int cg   = tid & 15;        // GEMM: 16 groups x 4 co
    const float* xbase = x + (size_t)b * C_ * H_ * W_;

    ull acc[4][4];
#pragma unroll
    for (int i = 0; i < 4; i++)
#pragma unroll
        for (int j = 0; j < 4; j++) acc[i][j] = 0ull;

    for (int c = 0; c < 18; c++) {
        const int n   = c >> 1;
        const int ci0 = (c & 1) * 32;
        __syncthreads();   // prev GEMM done reading (covers Phase A at c=0)

        // B chunk: w_s[kk][co], kk = local ci
        {
            const float4* src = (const float4*)(g_Wp + c * (CK * 64));
            float4* dst = (float4*)w_s;
#pragma unroll
            for (int j = 0; j < 4; j++)
                dst[j * 128 + tid] = src[j * 128 + tid];
        }

        // gather: meta once, 16 ci per thread
        {
            ushort4 q = s_q[n * 64 + px];
            float4  g = s_g[n * 64 + px];
#pragma unroll 4
            for (int i = 0; i < 16; i++) {
                int lk = half * 16 + i;          // local k row 0..31
                int ci = ci0 + lk;
                const float* xc = xbase + (ci << 12);
                float v = g.x * __ldg(xc + q.x) + g.y * __ldg(xc + q.y)
                        + g.z * __ldg(xc + q.z) + g.w * __ldg(xc + q.w);
                xo_s[lk * 64 + px] = v;
            }
        }
        __syncthreads();

        // GEMM chunk: 32 kk, 16 FFMA2/kk
#pragma unroll 4
        for (int kk = 0; kk < CK; kk++) {
            float4 a0 = *(const float4*)&xo_s[kk * 64 + pg * 8];
            float4 a1 = *(const float4*)&xo_s[kk * 64 + pg * 8 + 4];
            float4 w  = *(const float4*)&w_s[kk * 64 + cg * 4];
            ull a01 = ((const ull*)&a0)[0];
            ull a23 = ((const ull*)&a0)[1];
            ull a45 = ((const ull*)&a1)[0];
            ull a67 = ((const ull*)&a1)[1];
            ull w0 = dup2(w.x), w1 = dup2(w.y), w2 = dup2(w.z), w3 = dup2(w.w);
            ffma2(acc[0][0], w0, a01); ffma2(acc[0][1], w0, a23);
            ffma2(acc[0][2], w0, a45); ffma2(acc[0][3], w0, a67);
            ffma2(acc[1][0], w1, a01); ffma2(acc[1][1], w1, a23);
            ffma2(acc[1][2], w1, a45); ffma2(acc[1][3], w1, a67);
            ffma2(acc[2][0], w2, a01); ffma2(acc[2][1], w2, a23);
            ffma2(acc[2][2], w2, a45); ffma2(acc[2][3], w2, a67);
            ffma2(acc[3][0], w3, a01); ffma2(acc[3][1], w3, a23);
            ffma2(acc[3][2], w3, a45); ffma2(acc[3][3], w3, a67);
        }
    }

    // ---- Epilogue ----------------------------------------------------------
#pragma unroll
    for (int c = 0; c < 4; c++) {
        int co = cg * 4 + c;
        float* ob = &out[(((size_t)b * C_ + co) * H_ + h) * W_ + pg * 8];
        float2 p0 = unpack2(acc[c][0]);
        float2 p1 = unpack2(acc[c][1]);
        float2 p2 = unpack2(acc[c][2]);
        float2 p3 = unpack2(acc[c][3]);
        *(float4*)ob       = make_float4(p0.x, p0.y, p1.x, p1.y);
        *(float4*)(ob + 4) = make_float4(p2.x, p2.y, p3.x, p3.y);
    }
}

// ---------------------------------------------------------------------------
extern "C" void kernel_launch(void* const* d_in, const int* in_sizes, int n_in,
                              void* d_out, int out_size) {
    const float* x     = (const float*)d_in[0];
    const float* Woff  = (const float*)d_in[1];
    const float* boff  = (const float*)d_in[2];
    const float* Wconv = (const float*)d_in[3];
    float* out = (float*)d_out;

    cudaFuncSetAttribute(k1_offset_conv,
                         cudaFuncAttributeMaxDynamicSharedMemorySize, K1_SMEM);
    cudaFuncSetAttribute(k2_sample_gemm,
                         cudaFuncAttributeMaxDynamicSharedMemorySize, K2_SMEM);

    k1_offset_conv<<<dim3(4, 4, 9), 256, K1_SMEM>>>(x, Woff, boff, Wconv);
    k2_sample_gemm<<<dim3(H_, B_), 128, K2_SMEM>>>(x, out);
}